// round 11
// baseline (speedup 1.0000x reference)
#include <cuda_runtime.h>
#include <cuda_bf16.h>
#include <math.h>
#include <stdint.h>

// Problem constants (fixed per reference)
#define BSZ    4
#define TLEN   2048
#define DMODEL 1024
#define HEADS  16
#define HDIM   64
#define RAD    4
#define MROWS  (BSZ * TLEN)   // 8192

// ---------------------------------------------------------------------------
// Scratch (__device__ globals; no cudaMalloc allowed)
// ---------------------------------------------------------------------------
__device__ __align__(16) float g_qkv[(size_t)MROWS * 3 * DMODEL];
__device__ __align__(16) __nv_bfloat16 g_x_hi[(size_t)MROWS * DMODEL];
__device__ __align__(16) __nv_bfloat16 g_x_lo[(size_t)MROWS * DMODEL];
__device__ __align__(16) __nv_bfloat16 g_wq_hi[(size_t)3 * DMODEL * DMODEL];
__device__ __align__(16) __nv_bfloat16 g_wq_lo[(size_t)3 * DMODEL * DMODEL];
__device__ __align__(16) __nv_bfloat16 g_wp_hi[(size_t)DMODEL * DMODEL];
__device__ __align__(16) __nv_bfloat16 g_wp_lo[(size_t)DMODEL * DMODEL];
__device__ __align__(16) __nv_bfloat16 g_att_hi[(size_t)MROWS * DMODEL];
__device__ __align__(16) __nv_bfloat16 g_att_lo[(size_t)MROWS * DMODEL];

// ---------------------------------------------------------------------------
// PTX helpers
// ---------------------------------------------------------------------------
__device__ __forceinline__ void cp16(uint32_t dst, const void* src) {
    asm volatile("cp.async.cg.shared.global [%0], [%1], 16;" :: "r"(dst), "l"(src));
}
__device__ __forceinline__ void cp_commit() {
    asm volatile("cp.async.commit_group;" ::: "memory");
}
template <int N>
__device__ __forceinline__ void cp_wait() {
    asm volatile("cp.async.wait_group %0;" :: "n"(N) : "memory");
}
__device__ __forceinline__ void ldsm4(uint32_t* r, uint32_t addr) {
    asm volatile("ldmatrix.sync.aligned.m8n8.x4.shared.b16 {%0,%1,%2,%3}, [%4];"
                 : "=r"(r[0]), "=r"(r[1]), "=r"(r[2]), "=r"(r[3]) : "r"(addr));
}
__device__ __forceinline__ void mma16816(float* d, const uint32_t* a,
                                         uint32_t b0, uint32_t b1) {
    asm volatile(
        "mma.sync.aligned.m16n8k16.row.col.f32.bf16.bf16.f32 "
        "{%0,%1,%2,%3},{%4,%5,%6,%7},{%8,%9},{%0,%1,%2,%3};"
        : "+f"(d[0]), "+f"(d[1]), "+f"(d[2]), "+f"(d[3])
        : "r"(a[0]), "r"(a[1]), "r"(a[2]), "r"(a[3]), "r"(b0), "r"(b1));
}

// XOR swizzle: 16B chunk c within 64B row, rotated so 8 consecutive rows map to
// 8 distinct 16B bank-groups mod 128B -> conflict-free LDSM and STS.
#define SWZ(row, c) (((c) ^ (((row) >> 1) & 3)))

// ---------------------------------------------------------------------------
// bf16x3 split: fp32 -> (hi, lo) bf16 planes, 4 elems/thread
// ---------------------------------------------------------------------------
__global__ void split4(const float4* __restrict__ in,
                       __nv_bfloat162* __restrict__ hi,
                       __nv_bfloat162* __restrict__ lo, int n4)
{
    int i = blockIdx.x * blockDim.x + threadIdx.x;
    if (i >= n4) return;
    float4 v = in[i];
    __nv_bfloat16 hx = __float2bfloat16(v.x), hy = __float2bfloat16(v.y);
    __nv_bfloat16 hz = __float2bfloat16(v.z), hw = __float2bfloat16(v.w);
    __nv_bfloat162 h0; h0.x = hx; h0.y = hy;
    __nv_bfloat162 h1; h1.x = hz; h1.y = hw;
    __nv_bfloat162 l0, l1;
    l0.x = __float2bfloat16(v.x - __bfloat162float(hx));
    l0.y = __float2bfloat16(v.y - __bfloat162float(hy));
    l1.x = __float2bfloat16(v.z - __bfloat162float(hz));
    l1.y = __float2bfloat16(v.w - __bfloat162float(hw));
    hi[2 * i]     = h0;  hi[2 * i + 1] = h1;
    lo[2 * i]     = l0;  lo[2 * i + 1] = l1;
}

// ---------------------------------------------------------------------------
// Tensor-core GEMM (TN): C[M,N] = A[M,K] @ B[N,K]^T + bias, fp32-accurate via
// bf16x3: D += Ahi*Bhi + Ahi*Blo + Alo*Bhi (fp32 accumulate in HMMA).
// CTA tile 128x128x32, 8 warps (2x4) of 64x32.
// 3-stage cp.async pipeline (prefetch distance 2), 2 CTAs/SM.
// KEY (R11): term-major MMA ordering — the 3 bf16x3 terms for a given
// accumulator are issued 4 MMAs apart (distinct accumulators in between),
// breaking the accumulator RAW chain that capped the tensor pipe at 50%.
// ---------------------------------------------------------------------------
#define STAGE_BYTES 32768
#define NSTAGE 3
#define GEMM_SMEM (NSTAGE * STAGE_BYTES)

__global__ __launch_bounds__(256, 2)
void gemm_bf16x3(const __nv_bfloat16* __restrict__ Ahi,
                 const __nv_bfloat16* __restrict__ Alo,
                 const __nv_bfloat16* __restrict__ Bhi,
                 const __nv_bfloat16* __restrict__ Blo,
                 const float* __restrict__ bias,
                 float* __restrict__ C,
                 int M, int N, int K)
{
    extern __shared__ char smem[];
    const uint32_t sbase = (uint32_t)__cvta_generic_to_shared(smem);

    const int tid  = threadIdx.x;
    const int lane = tid & 31;
    const int warp = tid >> 5;
    const int bm = blockIdx.y * 128;
    const int bn = blockIdx.x * 128;
    const int wm = (warp >> 2) * 64;   // warp row offset in tile
    const int wn = (warp & 3) * 32;    // warp col offset in tile
    const int whalf = warp & 1;        // kk-order stagger

    // ---- cp.async mapping: thread covers row tid>>1, chunks {c0, c0+1} ----
    const int lrow = tid >> 1;
    const int c0   = (tid & 1) * 2;
    const __nv_bfloat16* srcs[4] = {
        Ahi + (size_t)(bm + lrow) * K,
        Alo + (size_t)(bm + lrow) * K,
        Bhi + (size_t)(bn + lrow) * K,
        Blo + (size_t)(bn + lrow) * K
    };
    const uint32_t sd0 = lrow * 64 + SWZ(lrow, c0) * 16;
    const uint32_t sd1 = lrow * 64 + SWZ(lrow, c0 + 1) * 16;

    auto load_stage = [&](int s, int k0) {
        const uint32_t base = sbase + s * STAGE_BYTES;
#pragma unroll
        for (int p = 0; p < 4; p++) {
            const __nv_bfloat16* g = srcs[p] + k0;
            cp16(base + p * 8192 + sd0, g + c0 * 8);
            cp16(base + p * 8192 + sd1, g + (c0 + 1) * 8);
        }
        cp_commit();
    };

    float acc[4][4][4];
#pragma unroll
    for (int i = 0; i < 4; i++)
#pragma unroll
        for (int j = 0; j < 4; j++)
#pragma unroll
            for (int k = 0; k < 4; k++) acc[i][j][k] = 0.f;

    const int NIT = K >> 5;            // 32
    load_stage(0, 0);
    load_stage(1, 32);

    const int r16 = lane & 15;
    const int khalf = lane >> 4;

#pragma unroll 1
    for (int it = 0; it < NIT; it++) {
        // Stage `it` must be complete; allow the younger group to stay pending.
        if (it + 1 < NIT) cp_wait<1>(); else cp_wait<0>();
        __syncthreads();   // also guarantees everyone finished compute(it-1)

        // Prefetch distance 2: overwrite buffer (it-1)%3, now provably idle.
        if (it + 2 < NIT) {
            int s2 = it + 2;
            s2 -= (s2 / 3) * 3;
            load_stage(s2, (it + 2) * 32);
        }

        const int s = it - (it / 3) * 3;
        const uint32_t stbase = sbase + s * STAGE_BYTES;

        // Two K16 halves; odd warps take them in reverse order.
#pragma unroll
        for (int kx = 0; kx < 2; kx++) {
            const int half = kx ^ whalf;
            const int kc = half * 2 + khalf;    // 16B chunk index 0..3

            uint32_t bh[2][4], bl[2][4];
#pragma unroll
            for (int ng = 0; ng < 2; ng++) {
                const int row = wn + ng * 16 + r16;
                const uint32_t off = row * 64 + SWZ(row, kc) * 16;
                ldsm4(bh[ng], stbase + 16384 + off);   // B_hi plane
                ldsm4(bl[ng], stbase + 24576 + off);   // B_lo plane
            }
            // Per-mb: load A frags, then issue the 12 MMAs TERM-MAJOR so
            // same-accumulator MMAs are 4 issues apart (no RAW chain).
#pragma unroll
            for (int mb = 0; mb < 4; mb++) {
                uint32_t ah[4], al[4];
                const int row = wm + mb * 16 + r16;
                const uint32_t off = row * 64 + SWZ(row, kc) * 16;
                ldsm4(ah, stbase + off);               // A_hi plane
                ldsm4(al, stbase + 8192 + off);        // A_lo plane
                // term 1: Ahi * Bhi  (4 distinct accumulators)
#pragma unroll
                for (int nb = 0; nb < 4; nb++) {
                    const int ng = nb >> 1, j = nb & 1;
                    mma16816(acc[mb][nb], ah, bh[ng][j], bh[ng][2 + j]);
                }
                // term 2: Ahi * Blo
#pragma unroll
                for (int nb = 0; nb < 4; nb++) {
                    const int ng = nb >> 1, j = nb & 1;
                    mma16816(acc[mb][nb], ah, bl[ng][j], bl[ng][2 + j]);
                }
                // term 3: Alo * Bhi
#pragma unroll
                for (int nb = 0; nb < 4; nb++) {
                    const int ng = nb >> 1, j = nb & 1;
                    mma16816(acc[mb][nb], al, bh[ng][j], bh[ng][2 + j]);
                }
            }
        }
    }

    // ---- Epilogue: bias add, fp32 stores ----
    const int g  = lane >> 2;
    const int t2 = (lane & 3) * 2;
#pragma unroll
    for (int nb = 0; nb < 4; nb++) {
        const int col = bn + wn + nb * 8 + t2;
        const float bx = __ldg(bias + col), by = __ldg(bias + col + 1);
#pragma unroll
        for (int mb = 0; mb < 4; mb++) {
            const int row = bm + wm + mb * 16 + g;
            float2 v0 = make_float2(acc[mb][nb][0] + bx, acc[mb][nb][1] + by);
            float2 v1 = make_float2(acc[mb][nb][2] + bx, acc[mb][nb][3] + by);
            *(float2*)(C + (size_t)row * N + col)       = v0;
            *(float2*)(C + (size_t)(row + 8) * N + col) = v1;
        }
    }
}

// ---------------------------------------------------------------------------
// Banded attention: one warp per (b,t,h), 9-key window, warp-shfl reductions.
// Reads fp32 qkv [bt][ q | D+k | 2D+v ]; writes output directly as bf16 hi/lo
// planes (feeding GEMM2 without an fp32 round trip).
// ---------------------------------------------------------------------------
__global__ __launch_bounds__(256)
void focal_attn(const float* __restrict__ qkv,
                __nv_bfloat16* __restrict__ out_hi,
                __nv_bfloat16* __restrict__ out_lo)
{
    const int warp = threadIdx.x >> 5;
    const int lane = threadIdx.x & 31;
    const int gw = blockIdx.x * 8 + warp;     // 0 .. B*T*H-1
    const int h  = gw & (HEADS - 1);
    const int bt = gw >> 4;
    const int t  = bt & (TLEN - 1);
    const int b  = bt >> 11;

    const size_t row_stride = 3 * DMODEL;
    const int doff = h * HDIM + lane * 2;

    const float2 q = *(const float2*)(qkv + (size_t)bt * row_stride + doff);

    float s[9];
#pragma unroll
    for (int jj = 0; jj < 9; jj++) {
        const int j = t - RAD + jj;
        float val = -INFINITY;
        if (j >= 0 && j < TLEN) {
            const float2 kv = *(const float2*)(
                qkv + (size_t)(b * TLEN + j) * row_stride + DMODEL + doff);
            float p = q.x * kv.x + q.y * kv.y;
#pragma unroll
            for (int o = 16; o > 0; o >>= 1)
                p += __shfl_xor_sync(0xffffffffu, p, o);
            val = p * 0.125f;   // hd^-0.5
        }
        s[jj] = val;
    }

    float m = s[0];
#pragma unroll
    for (int jj = 1; jj < 9; jj++) m = fmaxf(m, s[jj]);

    float p[9], psum = 0.f;
#pragma unroll
    for (int jj = 0; jj < 9; jj++) {
        p[jj] = (s[jj] == -INFINITY) ? 0.f : expf(s[jj] - m);
        psum += p[jj];
    }
    const float inv = 1.f / psum;

    float2 acc = make_float2(0.f, 0.f);
#pragma unroll
    for (int jj = 0; jj < 9; jj++) {
        const int j = t - RAD + jj;
        if (j >= 0 && j < TLEN) {
            const float2 vv = *(const float2*)(
                qkv + (size_t)(b * TLEN + j) * row_stride + 2 * DMODEL + doff);
            acc.x = fmaf(p[jj], vv.x, acc.x);
            acc.y = fmaf(p[jj], vv.y, acc.y);
        }
    }
    acc.x *= inv;
    acc.y *= inv;

    const __nv_bfloat16 hx = __float2bfloat16(acc.x);
    const __nv_bfloat16 hy = __float2bfloat16(acc.y);
    __nv_bfloat162 hp; hp.x = hx; hp.y = hy;
    __nv_bfloat162 lp;
    lp.x = __float2bfloat16(acc.x - __bfloat162float(hx));
    lp.y = __float2bfloat16(acc.y - __bfloat162float(hy));
    *(__nv_bfloat162*)(out_hi + (size_t)bt * DMODEL + doff) = hp;
    *(__nv_bfloat162*)(out_lo + (size_t)bt * DMODEL + doff) = lp;
}

// ---------------------------------------------------------------------------
// Launch: split inputs -> QKV GEMM (tensor) -> attention -> proj GEMM (tensor)
// ---------------------------------------------------------------------------
extern "C" void kernel_launch(void* const* d_in, const int* in_sizes, int n_in,
                              void* d_out, int out_size)
{
    const float* x      = (const float*)d_in[0];
    const float* w_qkv  = (const float*)d_in[1];
    const float* b_qkv  = (const float*)d_in[2];
    const float* w_proj = (const float*)d_in[3];
    const float* b_proj = (const float*)d_in[4];
    float* out = (float*)d_out;

    float *qkv;
    __nv_bfloat16 *xhi, *xlo, *wqhi, *wqlo, *wphi, *wplo, *athi, *atlo;
    cudaGetSymbolAddress((void**)&qkv,  g_qkv);
    cudaGetSymbolAddress((void**)&xhi,  g_x_hi);
    cudaGetSymbolAddress((void**)&xlo,  g_x_lo);
    cudaGetSymbolAddress((void**)&wqhi, g_wq_hi);
    cudaGetSymbolAddress((void**)&wqlo, g_wq_lo);
    cudaGetSymbolAddress((void**)&wphi, g_wp_hi);
    cudaGetSymbolAddress((void**)&wplo, g_wp_lo);
    cudaGetSymbolAddress((void**)&athi, g_att_hi);
    cudaGetSymbolAddress((void**)&atlo, g_att_lo);

    cudaFuncSetAttribute(gemm_bf16x3,
                         cudaFuncAttributeMaxDynamicSharedMemorySize, GEMM_SMEM);

    // Split fp32 inputs into bf16 hi/lo planes
    {
        int n4 = MROWS * DMODEL / 4;
        split4<<<(n4 + 255) / 256, 256>>>((const float4*)x,
                                          (__nv_bfloat162*)xhi, (__nv_bfloat162*)xlo, n4);
        n4 = 3 * DMODEL * DMODEL / 4;
        split4<<<(n4 + 255) / 256, 256>>>((const float4*)w_qkv,
                                          (__nv_bfloat162*)wqhi, (__nv_bfloat162*)wqlo, n4);
        n4 = DMODEL * DMODEL / 4;
        split4<<<(n4 + 255) / 256, 256>>>((const float4*)w_proj,
                                          (__nv_bfloat162*)wphi, (__nv_bfloat162*)wplo, n4);
    }

    // GEMM1: qkv[8192,3072] = x @ w_qkv^T + b_qkv
    {
        dim3 grid(3 * DMODEL / 128, MROWS / 128);   // 24 x 64
        gemm_bf16x3<<<grid, 256, GEMM_SMEM>>>(xhi, xlo, wqhi, wqlo, b_qkv, qkv,
                                              MROWS, 3 * DMODEL, DMODEL);
    }

    // Attention: B*T*H warps
    {
        const int total_warps = BSZ * TLEN * HEADS;
        focal_attn<<<total_warps / 8, 256>>>(qkv, athi, atlo);
    }

    // GEMM2: out[8192,1024] = att @ w_proj^T + b_proj
    {
        dim3 grid(DMODEL / 128, MROWS / 128);       // 8 x 64
        gemm_bf16x3<<<grid, 256, GEMM_SMEM>>>(athi, atlo, wphi, wplo, b_proj, out,
                                              MROWS, DMODEL, DMODEL);
    }
}

// round 12
// speedup vs baseline: 1.3793x; 1.3793x over previous
#include <cuda_runtime.h>
#include <cuda_fp16.h>
#include <math.h>
#include <stdint.h>

// Problem constants (fixed per reference)
#define BSZ    4
#define TLEN   2048
#define DMODEL 1024
#define HEADS  16
#define HDIM   64
#define RAD    4
#define MROWS  (BSZ * TLEN)   // 8192

// ---------------------------------------------------------------------------
// Scratch (__device__ globals; no cudaMalloc allowed)
// ---------------------------------------------------------------------------
__device__ __align__(16) float g_qkv[(size_t)MROWS * 3 * DMODEL];
__device__ __align__(16) __half g_x_hi[(size_t)MROWS * DMODEL];
__device__ __align__(16) __half g_wq_hi[(size_t)3 * DMODEL * DMODEL];
__device__ __align__(16) __half g_wq_lo[(size_t)3 * DMODEL * DMODEL];
__device__ __align__(16) __half g_wp_hi[(size_t)DMODEL * DMODEL];
__device__ __align__(16) __half g_wp_lo[(size_t)DMODEL * DMODEL];
__device__ __align__(16) __half g_att_hi[(size_t)MROWS * DMODEL];

// ---------------------------------------------------------------------------
// PTX helpers
// ---------------------------------------------------------------------------
__device__ __forceinline__ void cp16(uint32_t dst, const void* src) {
    asm volatile("cp.async.cg.shared.global [%0], [%1], 16;" :: "r"(dst), "l"(src));
}
__device__ __forceinline__ void cp_commit() {
    asm volatile("cp.async.commit_group;" ::: "memory");
}
template <int N>
__device__ __forceinline__ void cp_wait() {
    asm volatile("cp.async.wait_group %0;" :: "n"(N) : "memory");
}
__device__ __forceinline__ void ldsm4(uint32_t* r, uint32_t addr) {
    asm volatile("ldmatrix.sync.aligned.m8n8.x4.shared.b16 {%0,%1,%2,%3}, [%4];"
                 : "=r"(r[0]), "=r"(r[1]), "=r"(r[2]), "=r"(r[3]) : "r"(addr));
}
__device__ __forceinline__ void mma16816(float* d, const uint32_t* a,
                                         uint32_t b0, uint32_t b1) {
    asm volatile(
        "mma.sync.aligned.m16n8k16.row.col.f32.f16.f16.f32 "
        "{%0,%1,%2,%3},{%4,%5,%6,%7},{%8,%9},{%0,%1,%2,%3};"
        : "+f"(d[0]), "+f"(d[1]), "+f"(d[2]), "+f"(d[3])
        : "r"(a[0]), "r"(a[1]), "r"(a[2]), "r"(a[3]), "r"(b0), "r"(b1));
}

// XOR swizzle: 16B chunk c within 64B row, rotated so 8 consecutive rows map to
// 8 distinct 16B bank-groups mod 128B -> conflict-free LDSM and STS.
#define SWZ(row, c) (((c) ^ (((row) >> 1) & 3)))

// ---------------------------------------------------------------------------
// Splits: fp32 -> fp16 hi(+lo). Weights get hi/lo; activations hi only.
// ---------------------------------------------------------------------------
__global__ void split_w(const float4* __restrict__ in,
                        __half2* __restrict__ hi,
                        __half2* __restrict__ lo, int n4)
{
    int i = blockIdx.x * blockDim.x + threadIdx.x;
    if (i >= n4) return;
    float4 v = in[i];
    __half hx = __float2half(v.x), hy = __float2half(v.y);
    __half hz = __float2half(v.z), hw = __float2half(v.w);
    __half2 h0; h0.x = hx; h0.y = hy;
    __half2 h1; h1.x = hz; h1.y = hw;
    __half2 l0, l1;
    l0.x = __float2half(v.x - __half2float(hx));
    l0.y = __float2half(v.y - __half2float(hy));
    l1.x = __float2half(v.z - __half2float(hz));
    l1.y = __float2half(v.w - __half2float(hw));
    hi[2 * i] = h0;  hi[2 * i + 1] = h1;
    lo[2 * i] = l0;  lo[2 * i + 1] = l1;
}

__global__ void split_a(const float4* __restrict__ in,
                        __half2* __restrict__ hi, int n4)
{
    int i = blockIdx.x * blockDim.x + threadIdx.x;
    if (i >= n4) return;
    float4 v = in[i];
    __half2 h0; h0.x = __float2half(v.x); h0.y = __float2half(v.y);
    __half2 h1; h1.x = __float2half(v.z); h1.y = __float2half(v.w);
    hi[2 * i] = h0;  hi[2 * i + 1] = h1;
}

// ---------------------------------------------------------------------------
// Tensor-core GEMM (TN): C[M,N] = A[M,K] @ B[N,K]^T + bias, via fp16x2:
// D += Ah*Bh + Ah*Bl  (B split to 22 mantissa bits; A residual 2^-12 dropped).
// 2 MMAs per (tile,K16) -> 33% fewer HMMAs than bf16x3 at the same pipe cap.
// CTA tile 128x128x32, 8 warps (2x4) of 64x32; 3 smem planes per stage
// (Ah, Bh, Bl), 3-stage cp.async pipeline (prefetch distance 2), 2 CTAs/SM.
// Requires M%128==0, N%128==0, K%32==0 (true: 8192 x {3072,1024} x 1024).
// ---------------------------------------------------------------------------
#define STAGE_BYTES 24576
#define NSTAGE 3
#define GEMM_SMEM (NSTAGE * STAGE_BYTES)

__global__ __launch_bounds__(256, 2)
void gemm_fp16x2(const __half* __restrict__ Ah,
                 const __half* __restrict__ Bhi,
                 const __half* __restrict__ Blo,
                 const float* __restrict__ bias,
                 float* __restrict__ C,
                 int M, int N, int K)
{
    extern __shared__ char smem[];
    const uint32_t sbase = (uint32_t)__cvta_generic_to_shared(smem);

    const int tid  = threadIdx.x;
    const int lane = tid & 31;
    const int warp = tid >> 5;
    const int bm = blockIdx.y * 128;
    const int bn = blockIdx.x * 128;
    const int wm = (warp >> 2) * 64;   // warp row offset in tile
    const int wn = (warp & 3) * 32;    // warp col offset in tile
    const int whalf = warp & 1;        // kk-order stagger

    // ---- cp.async mapping: thread covers row tid>>1, chunks {c0, c0+1} ----
    const int lrow = tid >> 1;
    const int c0   = (tid & 1) * 2;
    const __half* srcs[3] = {
        Ah  + (size_t)(bm + lrow) * K,
        Bhi + (size_t)(bn + lrow) * K,
        Blo + (size_t)(bn + lrow) * K
    };
    const uint32_t sd0 = lrow * 64 + SWZ(lrow, c0) * 16;
    const uint32_t sd1 = lrow * 64 + SWZ(lrow, c0 + 1) * 16;

    auto load_stage = [&](int s, int k0) {
        const uint32_t base = sbase + s * STAGE_BYTES;
#pragma unroll
        for (int p = 0; p < 3; p++) {
            const __half* g = srcs[p] + k0;
            cp16(base + p * 8192 + sd0, g + c0 * 8);
            cp16(base + p * 8192 + sd1, g + (c0 + 1) * 8);
        }
        cp_commit();
    };

    float acc[4][4][4];
#pragma unroll
    for (int i = 0; i < 4; i++)
#pragma unroll
        for (int j = 0; j < 4; j++)
#pragma unroll
            for (int k = 0; k < 4; k++) acc[i][j][k] = 0.f;

    const int NIT = K >> 5;            // 32
    load_stage(0, 0);
    load_stage(1, 32);

    const int r16 = lane & 15;
    const int khalf = lane >> 4;

#pragma unroll 1
    for (int it = 0; it < NIT; it++) {
        // Stage `it` must be complete; allow the younger group to stay pending.
        if (it + 1 < NIT) cp_wait<1>(); else cp_wait<0>();
        __syncthreads();   // also guarantees everyone finished compute(it-1)

        // Prefetch distance 2: overwrite buffer (it-1)%3, now provably idle.
        if (it + 2 < NIT) {
            int s2 = it + 2;
            s2 -= (s2 / 3) * 3;
            load_stage(s2, (it + 2) * 32);
        }

        const int s = it - (it / 3) * 3;
        const uint32_t stbase = sbase + s * STAGE_BYTES;

        // Two K16 halves; odd warps take them in reverse order.
#pragma unroll
        for (int kx = 0; kx < 2; kx++) {
            const int half = kx ^ whalf;
            const int kc = half * 2 + khalf;    // 16B chunk index 0..3

            uint32_t bh[2][4], bl[2][4];
#pragma unroll
            for (int ng = 0; ng < 2; ng++) {
                const int row = wn + ng * 16 + r16;
                const uint32_t off = row * 64 + SWZ(row, kc) * 16;
                ldsm4(bh[ng], stbase + 8192 + off);    // B_hi plane
                ldsm4(bl[ng], stbase + 16384 + off);   // B_lo plane
            }
            // Per-mb: load A frag, then issue 8 MMAs term-major.
#pragma unroll
            for (int mb = 0; mb < 4; mb++) {
                uint32_t ah[4];
                const int row = wm + mb * 16 + r16;
                const uint32_t off = row * 64 + SWZ(row, kc) * 16;
                ldsm4(ah, stbase + off);               // A_hi plane
#pragma unroll
                for (int nb = 0; nb < 4; nb++) {
                    const int ng = nb >> 1, j = nb & 1;
                    mma16816(acc[mb][nb], ah, bh[ng][j], bh[ng][2 + j]);
                }
#pragma unroll
                for (int nb = 0; nb < 4; nb++) {
                    const int ng = nb >> 1, j = nb & 1;
                    mma16816(acc[mb][nb], ah, bl[ng][j], bl[ng][2 + j]);
                }
            }
        }
    }

    // ---- Epilogue: bias add, fp32 stores ----
    const int g  = lane >> 2;
    const int t2 = (lane & 3) * 2;
#pragma unroll
    for (int nb = 0; nb < 4; nb++) {
        const int col = bn + wn + nb * 8 + t2;
        const float bx = __ldg(bias + col), by = __ldg(bias + col + 1);
#pragma unroll
        for (int mb = 0; mb < 4; mb++) {
            const int row = bm + wm + mb * 16 + g;
            float2 v0 = make_float2(acc[mb][nb][0] + bx, acc[mb][nb][1] + by);
            float2 v1 = make_float2(acc[mb][nb][2] + bx, acc[mb][nb][3] + by);
            *(float2*)(C + (size_t)row * N + col)       = v0;
            *(float2*)(C + (size_t)(row + 8) * N + col) = v1;
        }
    }
}

// ---------------------------------------------------------------------------
// Banded attention: one warp per (b,t,h), 9-key window, warp-shfl reductions.
// Reads fp32 qkv [bt][ q | D+k | 2D+v ]; writes output as fp16 hi plane.
// ---------------------------------------------------------------------------
__global__ __launch_bounds__(256)
void focal_attn(const float* __restrict__ qkv,
                __half* __restrict__ out_hi)
{
    const int warp = threadIdx.x >> 5;
    const int lane = threadIdx.x & 31;
    const int gw = blockIdx.x * 8 + warp;     // 0 .. B*T*H-1
    const int h  = gw & (HEADS - 1);
    const int bt = gw >> 4;
    const int t  = bt & (TLEN - 1);
    const int b  = bt >> 11;

    const size_t row_stride = 3 * DMODEL;
    const int doff = h * HDIM + lane * 2;

    const float2 q = *(const float2*)(qkv + (size_t)bt * row_stride + doff);

    float s[9];
#pragma unroll
    for (int jj = 0; jj < 9; jj++) {
        const int j = t - RAD + jj;
        float val = -INFINITY;
        if (j >= 0 && j < TLEN) {
            const float2 kv = *(const float2*)(
                qkv + (size_t)(b * TLEN + j) * row_stride + DMODEL + doff);
            float p = q.x * kv.x + q.y * kv.y;
#pragma unroll
            for (int o = 16; o > 0; o >>= 1)
                p += __shfl_xor_sync(0xffffffffu, p, o);
            val = p * 0.125f;   // hd^-0.5
        }
        s[jj] = val;
    }

    float m = s[0];
#pragma unroll
    for (int jj = 1; jj < 9; jj++) m = fmaxf(m, s[jj]);

    float p[9], psum = 0.f;
#pragma unroll
    for (int jj = 0; jj < 9; jj++) {
        p[jj] = (s[jj] == -INFINITY) ? 0.f : expf(s[jj] - m);
        psum += p[jj];
    }
    const float inv = 1.f / psum;

    float2 acc = make_float2(0.f, 0.f);
#pragma unroll
    for (int jj = 0; jj < 9; jj++) {
        const int j = t - RAD + jj;
        if (j >= 0 && j < TLEN) {
            const float2 vv = *(const float2*)(
                qkv + (size_t)(b * TLEN + j) * row_stride + 2 * DMODEL + doff);
            acc.x = fmaf(p[jj], vv.x, acc.x);
            acc.y = fmaf(p[jj], vv.y, acc.y);
        }
    }
    acc.x *= inv;
    acc.y *= inv;

    __half2 hp;
    hp.x = __float2half(acc.x);
    hp.y = __float2half(acc.y);
    *(__half2*)(out_hi + (size_t)bt * DMODEL + doff) = hp;
}

// ---------------------------------------------------------------------------
// Launch: split inputs -> QKV GEMM (tensor) -> attention -> proj GEMM (tensor)
// ---------------------------------------------------------------------------
extern "C" void kernel_launch(void* const* d_in, const int* in_sizes, int n_in,
                              void* d_out, int out_size)
{
    const float* x      = (const float*)d_in[0];
    const float* w_qkv  = (const float*)d_in[1];
    const float* b_qkv  = (const float*)d_in[2];
    const float* w_proj = (const float*)d_in[3];
    const float* b_proj = (const float*)d_in[4];
    float* out = (float*)d_out;

    float *qkv;
    __half *xhi, *wqhi, *wqlo, *wphi, *wplo, *athi;
    cudaGetSymbolAddress((void**)&qkv,  g_qkv);
    cudaGetSymbolAddress((void**)&xhi,  g_x_hi);
    cudaGetSymbolAddress((void**)&wqhi, g_wq_hi);
    cudaGetSymbolAddress((void**)&wqlo, g_wq_lo);
    cudaGetSymbolAddress((void**)&wphi, g_wp_hi);
    cudaGetSymbolAddress((void**)&wplo, g_wp_lo);
    cudaGetSymbolAddress((void**)&athi, g_att_hi);

    cudaFuncSetAttribute(gemm_fp16x2,
                         cudaFuncAttributeMaxDynamicSharedMemorySize, GEMM_SMEM);

    // Split inputs: weights -> fp16 hi/lo; activations -> fp16 hi
    {
        int n4 = MROWS * DMODEL / 4;
        split_a<<<(n4 + 255) / 256, 256>>>((const float4*)x, (__half2*)xhi, n4);
        n4 = 3 * DMODEL * DMODEL / 4;
        split_w<<<(n4 + 255) / 256, 256>>>((const float4*)w_qkv,
                                           (__half2*)wqhi, (__half2*)wqlo, n4);
        n4 = DMODEL * DMODEL / 4;
        split_w<<<(n4 + 255) / 256, 256>>>((const float4*)w_proj,
                                           (__half2*)wphi, (__half2*)wplo, n4);
    }

    // GEMM1: qkv[8192,3072] = x @ w_qkv^T + b_qkv
    {
        dim3 grid(3 * DMODEL / 128, MROWS / 128);   // 24 x 64
        gemm_fp16x2<<<grid, 256, GEMM_SMEM>>>(xhi, wqhi, wqlo, b_qkv, qkv,
                                              MROWS, 3 * DMODEL, DMODEL);
    }

    // Attention: B*T*H warps
    {
        const int total_warps = BSZ * TLEN * HEADS;
        focal_attn<<<total_warps / 8, 256>>>(qkv, athi);
    }

    // GEMM2: out[8192,1024] = att @ w_proj^T + b_proj
    {
        dim3 grid(DMODEL / 128, MROWS / 128);       // 8 x 64
        gemm_fp16x2<<<grid, 256, GEMM_SMEM>>>(athi, wphi, wplo, b_proj, out,
                                              MROWS, DMODEL, DMODEL);
    }
}

// round 13
// speedup vs baseline: 2.0479x; 1.4847x over previous
#include <cuda_runtime.h>
#include <cuda_fp16.h>
#include <math.h>
#include <stdint.h>

// Problem constants (fixed per reference)
#define BSZ    4
#define TLEN   2048
#define DMODEL 1024
#define HEADS  16
#define HDIM   64
#define RAD    4
#define MROWS  (BSZ * TLEN)   // 8192

// ---------------------------------------------------------------------------
// Scratch (__device__ globals; no cudaMalloc allowed)
// ---------------------------------------------------------------------------
__device__ __align__(16) float g_qkv[(size_t)MROWS * 3 * DMODEL];
__device__ __align__(16) __half g_x_h[(size_t)MROWS * DMODEL];
__device__ __align__(16) __half g_wq_h[(size_t)3 * DMODEL * DMODEL];
__device__ __align__(16) __half g_wp_h[(size_t)DMODEL * DMODEL];
__device__ __align__(16) __half g_att_h[(size_t)MROWS * DMODEL];

// ---------------------------------------------------------------------------
// PTX helpers
// ---------------------------------------------------------------------------
__device__ __forceinline__ void cp16(uint32_t dst, const void* src) {
    asm volatile("cp.async.cg.shared.global [%0], [%1], 16;" :: "r"(dst), "l"(src));
}
__device__ __forceinline__ void cp_commit() {
    asm volatile("cp.async.commit_group;" ::: "memory");
}
template <int N>
__device__ __forceinline__ void cp_wait() {
    asm volatile("cp.async.wait_group %0;" :: "n"(N) : "memory");
}
__device__ __forceinline__ void ldsm4(uint32_t* r, uint32_t addr) {
    asm volatile("ldmatrix.sync.aligned.m8n8.x4.shared.b16 {%0,%1,%2,%3}, [%4];"
                 : "=r"(r[0]), "=r"(r[1]), "=r"(r[2]), "=r"(r[3]) : "r"(addr));
}
__device__ __forceinline__ void mma16816(float* d, const uint32_t* a,
                                         uint32_t b0, uint32_t b1) {
    asm volatile(
        "mma.sync.aligned.m16n8k16.row.col.f32.f16.f16.f32 "
        "{%0,%1,%2,%3},{%4,%5,%6,%7},{%8,%9},{%0,%1,%2,%3};"
        : "+f"(d[0]), "+f"(d[1]), "+f"(d[2]), "+f"(d[3])
        : "r"(a[0]), "r"(a[1]), "r"(a[2]), "r"(a[3]), "r"(b0), "r"(b1));
}

// XOR swizzle: 16B chunk c within 64B row, rotated so 8 consecutive rows map to
// 8 distinct 16B bank-groups mod 128B -> conflict-free LDSM and STS.
#define SWZ(row, c) (((c) ^ (((row) >> 1) & 3)))

// ---------------------------------------------------------------------------
// Cast fp32 -> fp16, 4 elems/thread
// ---------------------------------------------------------------------------
__global__ void cast_h(const float4* __restrict__ in,
                       __half2* __restrict__ hi, int n4)
{
    int i = blockIdx.x * blockDim.x + threadIdx.x;
    if (i >= n4) return;
    float4 v = in[i];
    __half2 h0; h0.x = __float2half(v.x); h0.y = __float2half(v.y);
    __half2 h1; h1.x = __float2half(v.z); h1.y = __float2half(v.w);
    hi[2 * i] = h0;  hi[2 * i + 1] = h1;
}

// ---------------------------------------------------------------------------
// Tensor-core GEMM (TN): C[M,N] = A[M,K] @ B[N,K]^T + bias, plain fp16 inputs
// with fp32 HMMA accumulate (1 MMA per 16x8xK16 step — minimal instruction
// count; the mma.sync path is issue-capped at ~50% tensor pipe, so time
// scales with MMA count).
// CTA tile 128x128x32, 8 warps (2x4) of 64x32; 2 smem planes per stage (A,B),
// 3-stage cp.async pipeline (prefetch distance 2), 2 CTAs/SM.
// Requires M%128==0, N%128==0, K%32==0 (true: 8192 x {3072,1024} x 1024).
// ---------------------------------------------------------------------------
#define STAGE_BYTES 16384
#define NSTAGE 3
#define GEMM_SMEM (NSTAGE * STAGE_BYTES)

__global__ __launch_bounds__(256, 2)
void gemm_fp16(const __half* __restrict__ A,
               const __half* __restrict__ B,
               const float* __restrict__ bias,
               float* __restrict__ C,
               int M, int N, int K)
{
    extern __shared__ char smem[];
    const uint32_t sbase = (uint32_t)__cvta_generic_to_shared(smem);

    const int tid  = threadIdx.x;
    const int lane = tid & 31;
    const int warp = tid >> 5;
    const int bm = blockIdx.y * 128;
    const int bn = blockIdx.x * 128;
    const int wm = (warp >> 2) * 64;   // warp row offset in tile
    const int wn = (warp & 3) * 32;    // warp col offset in tile
    const int whalf = warp & 1;        // kk-order stagger

    // ---- cp.async mapping: thread covers row tid>>1, chunks {c0, c0+1} ----
    const int lrow = tid >> 1;
    const int c0   = (tid & 1) * 2;
    const __half* srcs[2] = {
        A + (size_t)(bm + lrow) * K,
        B + (size_t)(bn + lrow) * K
    };
    const uint32_t sd0 = lrow * 64 + SWZ(lrow, c0) * 16;
    const uint32_t sd1 = lrow * 64 + SWZ(lrow, c0 + 1) * 16;

    auto load_stage = [&](int s, int k0) {
        const uint32_t base = sbase + s * STAGE_BYTES;
#pragma unroll
        for (int p = 0; p < 2; p++) {
            const __half* g = srcs[p] + k0;
            cp16(base + p * 8192 + sd0, g + c0 * 8);
            cp16(base + p * 8192 + sd1, g + (c0 + 1) * 8);
        }
        cp_commit();
    };

    float acc[4][4][4];
#pragma unroll
    for (int i = 0; i < 4; i++)
#pragma unroll
        for (int j = 0; j < 4; j++)
#pragma unroll
            for (int k = 0; k < 4; k++) acc[i][j][k] = 0.f;

    const int NIT = K >> 5;            // 32
    load_stage(0, 0);
    load_stage(1, 32);

    const int r16 = lane & 15;
    const int khalf = lane >> 4;

#pragma unroll 1
    for (int it = 0; it < NIT; it++) {
        // Stage `it` must be complete; allow the younger group to stay pending.
        if (it + 1 < NIT) cp_wait<1>(); else cp_wait<0>();
        __syncthreads();   // also guarantees everyone finished compute(it-1)

        // Prefetch distance 2: overwrite buffer (it-1)%3, now provably idle.
        if (it + 2 < NIT) {
            int s2 = it + 2;
            s2 -= (s2 / 3) * 3;
            load_stage(s2, (it + 2) * 32);
        }

        const int s = it - (it / 3) * 3;
        const uint32_t stbase = sbase + s * STAGE_BYTES;

        // Two K16 halves; odd warps take them in reverse order.
#pragma unroll
        for (int kx = 0; kx < 2; kx++) {
            const int half = kx ^ whalf;
            const int kc = half * 2 + khalf;    // 16B chunk index 0..3

            uint32_t bfr[2][4];
#pragma unroll
            for (int ng = 0; ng < 2; ng++) {
                const int row = wn + ng * 16 + r16;
                const uint32_t off = row * 64 + SWZ(row, kc) * 16;
                ldsm4(bfr[ng], stbase + 8192 + off);   // B plane
            }
            // Per-mb: load A frag, then 4 MMAs (distinct accumulators).
#pragma unroll
            for (int mb = 0; mb < 4; mb++) {
                uint32_t afr[4];
                const int row = wm + mb * 16 + r16;
                const uint32_t off = row * 64 + SWZ(row, kc) * 16;
                ldsm4(afr, stbase + off);              // A plane
#pragma unroll
                for (int nb = 0; nb < 4; nb++) {
                    const int ng = nb >> 1, j = nb & 1;
                    mma16816(acc[mb][nb], afr, bfr[ng][j], bfr[ng][2 + j]);
                }
            }
        }
    }

    // ---- Epilogue: bias add, fp32 stores ----
    const int g  = lane >> 2;
    const int t2 = (lane & 3) * 2;
#pragma unroll
    for (int nb = 0; nb < 4; nb++) {
        const int col = bn + wn + nb * 8 + t2;
        const float bx = __ldg(bias + col), by = __ldg(bias + col + 1);
#pragma unroll
        for (int mb = 0; mb < 4; mb++) {
            const int row = bm + wm + mb * 16 + g;
            float2 v0 = make_float2(acc[mb][nb][0] + bx, acc[mb][nb][1] + by);
            float2 v1 = make_float2(acc[mb][nb][2] + bx, acc[mb][nb][3] + by);
            *(float2*)(C + (size_t)row * N + col)       = v0;
            *(float2*)(C + (size_t)(row + 8) * N + col) = v1;
        }
    }
}

// ---------------------------------------------------------------------------
// Banded attention: one warp per (b,t,h), 9-key window, warp-shfl reductions.
// Reads fp32 qkv [bt][ q | D+k | 2D+v ]; writes output as fp16 plane.
// ---------------------------------------------------------------------------
__global__ __launch_bounds__(256)
void focal_attn(const float* __restrict__ qkv,
                __half* __restrict__ out_h)
{
    const int warp = threadIdx.x >> 5;
    const int lane = threadIdx.x & 31;
    const int gw = blockIdx.x * 8 + warp;     // 0 .. B*T*H-1
    const int h  = gw & (HEADS - 1);
    const int bt = gw >> 4;
    const int t  = bt & (TLEN - 1);
    const int b  = bt >> 11;

    const size_t row_stride = 3 * DMODEL;
    const int doff = h * HDIM + lane * 2;

    const float2 q = *(const float2*)(qkv + (size_t)bt * row_stride + doff);

    float s[9];
#pragma unroll
    for (int jj = 0; jj < 9; jj++) {
        const int j = t - RAD + jj;
        float val = -INFINITY;
        if (j >= 0 && j < TLEN) {
            const float2 kv = *(const float2*)(
                qkv + (size_t)(b * TLEN + j) * row_stride + DMODEL + doff);
            float p = q.x * kv.x + q.y * kv.y;
#pragma unroll
            for (int o = 16; o > 0; o >>= 1)
                p += __shfl_xor_sync(0xffffffffu, p, o);
            val = p * 0.125f;   // hd^-0.5
        }
        s[jj] = val;
    }

    float m = s[0];
#pragma unroll
    for (int jj = 1; jj < 9; jj++) m = fmaxf(m, s[jj]);

    float p[9], psum = 0.f;
#pragma unroll
    for (int jj = 0; jj < 9; jj++) {
        p[jj] = (s[jj] == -INFINITY) ? 0.f : expf(s[jj] - m);
        psum += p[jj];
    }
    const float inv = 1.f / psum;

    float2 acc = make_float2(0.f, 0.f);
#pragma unroll
    for (int jj = 0; jj < 9; jj++) {
        const int j = t - RAD + jj;
        if (j >= 0 && j < TLEN) {
            const float2 vv = *(const float2*)(
                qkv + (size_t)(b * TLEN + j) * row_stride + 2 * DMODEL + doff);
            acc.x = fmaf(p[jj], vv.x, acc.x);
            acc.y = fmaf(p[jj], vv.y, acc.y);
        }
    }
    acc.x *= inv;
    acc.y *= inv;

    __half2 hp;
    hp.x = __float2half(acc.x);
    hp.y = __float2half(acc.y);
    *(__half2*)(out_h + (size_t)bt * DMODEL + doff) = hp;
}

// ---------------------------------------------------------------------------
// Launch: cast inputs -> QKV GEMM (tensor) -> attention -> proj GEMM (tensor)
// ---------------------------------------------------------------------------
extern "C" void kernel_launch(void* const* d_in, const int* in_sizes, int n_in,
                              void* d_out, int out_size)
{
    const float* x      = (const float*)d_in[0];
    const float* w_qkv  = (const float*)d_in[1];
    const float* b_qkv  = (const float*)d_in[2];
    const float* w_proj = (const float*)d_in[3];
    const float* b_proj = (const float*)d_in[4];
    float* out = (float*)d_out;

    float *qkv;
    __half *xh, *wqh, *wph, *ath;
    cudaGetSymbolAddress((void**)&qkv, g_qkv);
    cudaGetSymbolAddress((void**)&xh,  g_x_h);
    cudaGetSymbolAddress((void**)&wqh, g_wq_h);
    cudaGetSymbolAddress((void**)&wph, g_wp_h);
    cudaGetSymbolAddress((void**)&ath, g_att_h);

    cudaFuncSetAttribute(gemm_fp16,
                         cudaFuncAttributeMaxDynamicSharedMemorySize, GEMM_SMEM);

    // Cast inputs to fp16
    {
        int n4 = MROWS * DMODEL / 4;
        cast_h<<<(n4 + 255) / 256, 256>>>((const float4*)x, (__half2*)xh, n4);
        n4 = 3 * DMODEL * DMODEL / 4;
        cast_h<<<(n4 + 255) / 256, 256>>>((const float4*)w_qkv, (__half2*)wqh, n4);
        n4 = DMODEL * DMODEL / 4;
        cast_h<<<(n4 + 255) / 256, 256>>>((const float4*)w_proj, (__half2*)wph, n4);
    }

    // GEMM1: qkv[8192,3072] = x @ w_qkv^T + b_qkv
    {
        dim3 grid(3 * DMODEL / 128, MROWS / 128);   // 24 x 64
        gemm_fp16<<<grid, 256, GEMM_SMEM>>>(xh, wqh, b_qkv, qkv,
                                            MROWS, 3 * DMODEL, DMODEL);
    }

    // Attention: B*T*H warps
    {
        const int total_warps = BSZ * TLEN * HEADS;
        focal_attn<<<total_warps / 8, 256>>>(qkv, ath);
    }

    // GEMM2: out[8192,1024] = att @ w_proj^T + b_proj
    {
        dim3 grid(DMODEL / 128, MROWS / 128);       // 8 x 64
        gemm_fp16<<<grid, 256, GEMM_SMEM>>>(ath, wph, b_proj, out,
                                            MROWS, DMODEL, DMODEL);
    }
}

// round 14
// speedup vs baseline: 2.0589x; 1.0054x over previous
#include <cuda_runtime.h>
#include <cuda_fp16.h>
#include <math.h>
#include <stdint.h>

// Problem constants (fixed per reference)
#define BSZ    4
#define TLEN   2048
#define DMODEL 1024
#define HEADS  16
#define HDIM   64
#define RAD    4
#define MROWS  (BSZ * TLEN)   // 8192

// ---------------------------------------------------------------------------
// Scratch (__device__ globals; no cudaMalloc allowed)
// ---------------------------------------------------------------------------
__device__ __align__(16) __half g_qkv_h[(size_t)MROWS * 3 * DMODEL];  // 48 MB
__device__ __align__(16) __half g_x_h[(size_t)MROWS * DMODEL];
__device__ __align__(16) __half g_wq_h[(size_t)3 * DMODEL * DMODEL];
__device__ __align__(16) __half g_wp_h[(size_t)DMODEL * DMODEL];
__device__ __align__(16) __half g_att_h[(size_t)MROWS * DMODEL];

// ---------------------------------------------------------------------------
// PTX helpers
// ---------------------------------------------------------------------------
__device__ __forceinline__ void cp16(uint32_t dst, const void* src) {
    asm volatile("cp.async.cg.shared.global [%0], [%1], 16;" :: "r"(dst), "l"(src));
}
__device__ __forceinline__ void cp_commit() {
    asm volatile("cp.async.commit_group;" ::: "memory");
}
template <int N>
__device__ __forceinline__ void cp_wait() {
    asm volatile("cp.async.wait_group %0;" :: "n"(N) : "memory");
}
__device__ __forceinline__ void ldsm4(uint32_t* r, uint32_t addr) {
    asm volatile("ldmatrix.sync.aligned.m8n8.x4.shared.b16 {%0,%1,%2,%3}, [%4];"
                 : "=r"(r[0]), "=r"(r[1]), "=r"(r[2]), "=r"(r[3]) : "r"(addr));
}
__device__ __forceinline__ void mma16816(float* d, const uint32_t* a,
                                         uint32_t b0, uint32_t b1) {
    asm volatile(
        "mma.sync.aligned.m16n8k16.row.col.f32.f16.f16.f32 "
        "{%0,%1,%2,%3},{%4,%5,%6,%7},{%8,%9},{%0,%1,%2,%3};"
        : "+f"(d[0]), "+f"(d[1]), "+f"(d[2]), "+f"(d[3])
        : "r"(a[0]), "r"(a[1]), "r"(a[2]), "r"(a[3]), "r"(b0), "r"(b1));
}

// SW128 swizzle over 128B rows: 16B chunk c (0..7) XOR row&7 -> conflict-free
// LDSM and cp.async stores (8 consecutive rows hit 8 distinct 16B bank-groups).
#define SWZ8(row, c) (((c) ^ ((row) & 7)))

// ---------------------------------------------------------------------------
// Cast fp32 -> fp16, 4 elems/thread
// ---------------------------------------------------------------------------
__global__ void cast_h(const float4* __restrict__ in,
                       __half2* __restrict__ hi, int n4)
{
    int i = blockIdx.x * blockDim.x + threadIdx.x;
    if (i >= n4) return;
    float4 v = in[i];
    __half2 h0; h0.x = __float2half(v.x); h0.y = __float2half(v.y);
    __half2 h1; h1.x = __float2half(v.z); h1.y = __float2half(v.w);
    hi[2 * i] = h0;  hi[2 * i + 1] = h1;
}

// ---------------------------------------------------------------------------
// Tensor-core GEMM (TN): C[M,N] = A[M,K] @ B[N,K]^T + bias, fp16 in, fp32 acc.
// CTA tile 128x128x64 (BK=64: 16 iters, amortizes the ~1400cyc/iter fixed
// overhead over 2x the MMA work). 8 warps (2x4) of 64x32.
// 2 smem planes per stage (A,B), each 128 rows x 128B SW128; 3 stages,
// prefetch distance 2, 2 CTAs/SM (192KB smem, regs<=128).
// HALF_OUT: fp16 C stores (GEMM1 -> qkv) vs fp32 (GEMM2 -> output).
// ---------------------------------------------------------------------------
#define STAGE_BYTES 32768
#define NSTAGE 3
#define GEMM_SMEM (NSTAGE * STAGE_BYTES)

template <bool HALF_OUT>
__global__ __launch_bounds__(256, 2)
void gemm_fp16(const __half* __restrict__ A,
               const __half* __restrict__ B,
               const float* __restrict__ bias,
               void* __restrict__ Cv,
               int M, int N, int K)
{
    extern __shared__ char smem[];
    const uint32_t sbase = (uint32_t)__cvta_generic_to_shared(smem);

    const int tid  = threadIdx.x;
    const int lane = tid & 31;
    const int warp = tid >> 5;
    const int bm = blockIdx.y * 128;
    const int bn = blockIdx.x * 128;
    const int wm = (warp >> 2) * 64;   // warp row offset in tile
    const int wn = (warp & 3) * 32;    // warp col offset in tile

    // ---- cp.async: thread -> row tid>>1, 4 of the 8 chunks per 128B row ----
    const int lrow = tid >> 1;
    const int c0   = (tid & 1) * 4;
    const __half* srcA = A + (size_t)(bm + lrow) * K;
    const __half* srcB = B + (size_t)(bn + lrow) * K;
    uint32_t sd[4];
#pragma unroll
    for (int j = 0; j < 4; j++)
        sd[j] = (uint32_t)(lrow * 128 + SWZ8(lrow, c0 + j) * 16);

    auto load_stage = [&](int s, int k0) {
        const uint32_t base = sbase + s * STAGE_BYTES;
#pragma unroll
        for (int j = 0; j < 4; j++)
            cp16(base + sd[j], srcA + k0 + (c0 + j) * 8);
#pragma unroll
        for (int j = 0; j < 4; j++)
            cp16(base + 16384 + sd[j], srcB + k0 + (c0 + j) * 8);
        cp_commit();
    };

    float acc[4][4][4];
#pragma unroll
    for (int i = 0; i < 4; i++)
#pragma unroll
        for (int j = 0; j < 4; j++)
#pragma unroll
            for (int k = 0; k < 4; k++) acc[i][j][k] = 0.f;

    const int NIT = K >> 6;            // 16
    load_stage(0, 0);
    load_stage(1, 64);

    const int r16 = lane & 15;
    const int khalf = lane >> 4;
    const int wrot = warp & 3;         // kk-order stagger across warps

#pragma unroll 1
    for (int it = 0; it < NIT; it++) {
        if (it + 1 < NIT) cp_wait<1>(); else cp_wait<0>();
        __syncthreads();

        if (it + 2 < NIT) {
            int s2 = it + 2;
            s2 -= (s2 / 3) * 3;
            load_stage(s2, (it + 2) * 64);
        }

        const int s = it - (it / 3) * 3;
        const uint32_t stbase = sbase + s * STAGE_BYTES;

        // Four K16 steps; warps start at different steps (anti-convoy).
#pragma unroll
        for (int kx = 0; kx < 4; kx++) {
            const int kk = (kx + wrot) & 3;
            const int kc = kk * 2 + khalf;      // 16B chunk index 0..7

            uint32_t bfr[2][4];
#pragma unroll
            for (int ng = 0; ng < 2; ng++) {
                const int row = wn + ng * 16 + r16;
                const uint32_t off = row * 128 + SWZ8(row, kc) * 16;
                ldsm4(bfr[ng], stbase + 16384 + off);  // B plane
            }
#pragma unroll
            for (int mb = 0; mb < 4; mb++) {
                uint32_t afr[4];
                const int row = wm + mb * 16 + r16;
                const uint32_t off = row * 128 + SWZ8(row, kc) * 16;
                ldsm4(afr, stbase + off);              // A plane
#pragma unroll
                for (int nb = 0; nb < 4; nb++) {
                    const int ng = nb >> 1, j = nb & 1;
                    mma16816(acc[mb][nb], afr, bfr[ng][j], bfr[ng][2 + j]);
                }
            }
        }
    }

    // ---- Epilogue: bias add; fp16 or fp32 stores ----
    const int g  = lane >> 2;
    const int t2 = (lane & 3) * 2;
#pragma unroll
    for (int nb = 0; nb < 4; nb++) {
        const int col = bn + wn + nb * 8 + t2;
        const float bx = __ldg(bias + col), by = __ldg(bias + col + 1);
#pragma unroll
        for (int mb = 0; mb < 4; mb++) {
            const int row = bm + wm + mb * 16 + g;
            if (HALF_OUT) {
                __half* C = (__half*)Cv;
                __half2 v0, v1;
                v0.x = __float2half(acc[mb][nb][0] + bx);
                v0.y = __float2half(acc[mb][nb][1] + by);
                v1.x = __float2half(acc[mb][nb][2] + bx);
                v1.y = __float2half(acc[mb][nb][3] + by);
                *(__half2*)(C + (size_t)row * N + col)       = v0;
                *(__half2*)(C + (size_t)(row + 8) * N + col) = v1;
            } else {
                float* C = (float*)Cv;
                float2 v0 = make_float2(acc[mb][nb][0] + bx, acc[mb][nb][1] + by);
                float2 v1 = make_float2(acc[mb][nb][2] + bx, acc[mb][nb][3] + by);
                *(float2*)(C + (size_t)row * N + col)       = v0;
                *(float2*)(C + (size_t)(row + 8) * N + col) = v1;
            }
        }
    }
}

// ---------------------------------------------------------------------------
// Banded attention: one warp per (b,t,h), 9-key window, warp-shfl reductions.
// Reads fp16 qkv [bt][ q | D+k | 2D+v ] (fp32 math); writes fp16 plane.
// ---------------------------------------------------------------------------
__global__ __launch_bounds__(256)
void focal_attn(const __half* __restrict__ qkv,
                __half* __restrict__ out_h)
{
    const int warp = threadIdx.x >> 5;
    const int lane = threadIdx.x & 31;
    const int gw = blockIdx.x * 8 + warp;     // 0 .. B*T*H-1
    const int h  = gw & (HEADS - 1);
    const int bt = gw >> 4;
    const int t  = bt & (TLEN - 1);
    const int b  = bt >> 11;

    const size_t row_stride = 3 * DMODEL;
    const int doff = h * HDIM + lane * 2;

    const float2 q = __half22float2(
        *(const __half2*)(qkv + (size_t)bt * row_stride + doff));

    float s[9];
#pragma unroll
    for (int jj = 0; jj < 9; jj++) {
        const int j = t - RAD + jj;
        float val = -INFINITY;
        if (j >= 0 && j < TLEN) {
            const float2 kv = __half22float2(*(const __half2*)(
                qkv + (size_t)(b * TLEN + j) * row_stride + DMODEL + doff));
            float p = q.x * kv.x + q.y * kv.y;
#pragma unroll
            for (int o = 16; o > 0; o >>= 1)
                p += __shfl_xor_sync(0xffffffffu, p, o);
            val = p * 0.125f;   // hd^-0.5
        }
        s[jj] = val;
    }

    float m = s[0];
#pragma unroll
    for (int jj = 1; jj < 9; jj++) m = fmaxf(m, s[jj]);

    float p[9], psum = 0.f;
#pragma unroll
    for (int jj = 0; jj < 9; jj++) {
        p[jj] = (s[jj] == -INFINITY) ? 0.f : expf(s[jj] - m);
        psum += p[jj];
    }
    const float inv = 1.f / psum;

    float2 acc = make_float2(0.f, 0.f);
#pragma unroll
    for (int jj = 0; jj < 9; jj++) {
        const int j = t - RAD + jj;
        if (j >= 0 && j < TLEN) {
            const float2 vv = __half22float2(*(const __half2*)(
                qkv + (size_t)(b * TLEN + j) * row_stride + 2 * DMODEL + doff));
            acc.x = fmaf(p[jj], vv.x, acc.x);
            acc.y = fmaf(p[jj], vv.y, acc.y);
        }
    }
    acc.x *= inv;
    acc.y *= inv;

    __half2 hp;
    hp.x = __float2half(acc.x);
    hp.y = __float2half(acc.y);
    *(__half2*)(out_h + (size_t)bt * DMODEL + doff) = hp;
}

// ---------------------------------------------------------------------------
// Launch: cast inputs -> QKV GEMM (fp16 out) -> attention -> proj GEMM
// ---------------------------------------------------------------------------
extern "C" void kernel_launch(void* const* d_in, const int* in_sizes, int n_in,
                              void* d_out, int out_size)
{
    const float* x      = (const float*)d_in[0];
    const float* w_qkv  = (const float*)d_in[1];
    const float* b_qkv  = (const float*)d_in[2];
    const float* w_proj = (const float*)d_in[3];
    const float* b_proj = (const float*)d_in[4];
    float* out = (float*)d_out;

    __half *qkvh, *xh, *wqh, *wph, *ath;
    cudaGetSymbolAddress((void**)&qkvh, g_qkv_h);
    cudaGetSymbolAddress((void**)&xh,  g_x_h);
    cudaGetSymbolAddress((void**)&wqh, g_wq_h);
    cudaGetSymbolAddress((void**)&wph, g_wp_h);
    cudaGetSymbolAddress((void**)&ath, g_att_h);

    cudaFuncSetAttribute(gemm_fp16<true>,
                         cudaFuncAttributeMaxDynamicSharedMemorySize, GEMM_SMEM);
    cudaFuncSetAttribute(gemm_fp16<false>,
                         cudaFuncAttributeMaxDynamicSharedMemorySize, GEMM_SMEM);

    // Cast inputs to fp16
    {
        int n4 = MROWS * DMODEL / 4;
        cast_h<<<(n4 + 255) / 256, 256>>>((const float4*)x, (__half2*)xh, n4);
        n4 = 3 * DMODEL * DMODEL / 4;
        cast_h<<<(n4 + 255) / 256, 256>>>((const float4*)w_qkv, (__half2*)wqh, n4);
        n4 = DMODEL * DMODEL / 4;
        cast_h<<<(n4 + 255) / 256, 256>>>((const float4*)w_proj, (__half2*)wph, n4);
    }

    // GEMM1: qkv[8192,3072] = x @ w_qkv^T + b_qkv  (fp16 out)
    {
        dim3 grid(3 * DMODEL / 128, MROWS / 128);   // 24 x 64
        gemm_fp16<true><<<grid, 256, GEMM_SMEM>>>(xh, wqh, b_qkv, qkvh,
                                                  MROWS, 3 * DMODEL, DMODEL);
    }

    // Attention: B*T*H warps
    {
        const int total_warps = BSZ * TLEN * HEADS;
        focal_attn<<<total_warps / 8, 256>>>(qkvh, ath);
    }

    // GEMM2: out[8192,1024] = att @ w_proj^T + b_proj  (fp32 out)
    {
        dim3 grid(DMODEL / 128, MROWS / 128);       // 8 x 64
        gemm_fp16<false><<<grid, 256, GEMM_SMEM>>>(ath, wph, b_proj, out,
                                                   MROWS, DMODEL, DMODEL);
    }
}